// round 4
// baseline (speedup 1.0000x reference)
#include <cuda_runtime.h>

#define T_DATA 100000
#define N_E    500
#define N_I    200
#define SUB    20
#define NB     3
#define TSYN   201

// Scratch (allocation-free rule: device globals).
// g_in2[s*T + t] packs (in_e, in_i) as two f32 lanes in one 64-bit word.
__device__ unsigned long long g_in2[(size_t)SUB * T_DATA];
// g_kern2[s*TSYN + k] packs (kern_e, kern_i).
__device__ unsigned long long g_kern2[SUB * TSYN];

// ---- packed f32x2 helpers ----
__device__ __forceinline__ unsigned long long pk2(float lo, float hi) {
    unsigned long long r;
    asm("mov.b64 %0, {%1, %2};" : "=l"(r) : "f"(lo), "f"(hi));
    return r;
}
__device__ __forceinline__ void upk2(unsigned long long v, float& lo, float& hi) {
    asm("mov.b64 {%0, %1}, %2;" : "=f"(lo), "=f"(hi) : "l"(v));
}
__device__ __forceinline__ void fma2(unsigned long long& d, unsigned long long a,
                                     unsigned long long b) {
    asm("fma.rn.f32x2 %0, %1, %2, %0;" : "+l"(d) : "l"(a), "l"(b));
}

// ---------------------------------------------------------------------------
// Kernel bank: kern[s,c,k] = sum_b K_syn[s,b,c] * tt*exp(-tt),
//   tt = max(k - delta[s,c], 0) / exp(tau[b,c]).   8040 values total.
// ---------------------------------------------------------------------------
__global__ void kern_build(const float* __restrict__ K_syn,
                           const float* __restrict__ tau_syn,
                           const float* __restrict__ delta_syn) {
    int idx = blockIdx.x * blockDim.x + threadIdx.x;
    if (idx >= SUB * TSYN * 2) return;
    int c = idx & 1;
    int k = (idx >> 1) % TSYN;
    int s = idx / (TSYN * 2);
    float ts = (float)k - delta_syn[s * 2 + c];
    ts = fmaxf(ts, 0.0f);
    float acc = 0.0f;
#pragma unroll
    for (int b = 0; b < NB; b++) {
        float tau = expf(tau_syn[b * 2 + c]);
        float tt = ts / tau;
        acc += K_syn[s * 6 + b * 2 + c] * tt * expf(-tt);
    }
    reinterpret_cast<float*>(g_kern2)[(s * TSYN + k) * 2 + c] = acc;
}

// ---------------------------------------------------------------------------
// Tall-skinny GEMM: in[t,s] = sum_j S[t,j] * C[s,j].
// Block: 64 threads x 4 rows = 256 time rows. K staged in chunks of 20.
// S tile stored TRANSPOSED in smem so each thread LDS.128's its 4-row pack;
// rows packed pairwise into f32x2; C duplicated into both lanes.
// Writes lane CIDX (0=e, 1=i) of the interleaved scratch.
// ---------------------------------------------------------------------------
template <int NIN, int CIDX>
__global__ __launch_bounds__(64) void gemm_kernel(const float* __restrict__ Sg,
                                                  const float* __restrict__ Cg) {
    __shared__ float S_sh[20][256];               // [k_local][row]
    __shared__ unsigned long long C_sh[20][20];   // [s][k_local], value duplicated

    const int tid = threadIdx.x;
    const int t0 = blockIdx.x * 256;

    unsigned long long acc_a[SUB], acc_b[SUB];
#pragma unroll
    for (int s = 0; s < SUB; s++) { acc_a[s] = 0ULL; acc_b[s] = 0ULL; }

    for (int kc = 0; kc < NIN; kc += 20) {
        __syncthreads();
        // C chunk, duplicated into both f32x2 lanes
        for (int i = tid; i < SUB * 20; i += 64) {
            int s = i / 20, c = i % 20;
            float v = Cg[s * NIN + kc + c];
            C_sh[s][c] = pk2(v, v);
        }
        // S tile (256 rows x 20 cols) -> transposed smem. 1280 float4s / 64 thr.
#pragma unroll
        for (int it = 0; it < 20; it++) {
            int idx4 = it * 64 + tid;
            int c4 = idx4 >> 8;      // 0..4
            int r  = idx4 & 255;     // 0..255
            float4 v = make_float4(0.f, 0.f, 0.f, 0.f);
            if (t0 + r < T_DATA)
                v = *reinterpret_cast<const float4*>(
                        Sg + (size_t)(t0 + r) * NIN + kc + 4 * c4);
            S_sh[4 * c4 + 0][r] = v.x;
            S_sh[4 * c4 + 1][r] = v.y;
            S_sh[4 * c4 + 2][r] = v.z;
            S_sh[4 * c4 + 3][r] = v.w;
        }
        __syncthreads();

#pragma unroll 4
        for (int c = 0; c < 20; c++) {
            float4 x = *reinterpret_cast<const float4*>(&S_sh[c][4 * tid]);
            unsigned long long xa = pk2(x.x, x.y);
            unsigned long long xb = pk2(x.z, x.w);
#pragma unroll
            for (int s = 0; s < SUB; s++) {
                unsigned long long cc = C_sh[s][c];
                fma2(acc_a[s], xa, cc);
                fma2(acc_b[s], xb, cc);
            }
        }
    }

    // Epilogue: scatter into interleaved transposed scratch [s][t][{e,i}]
    float* gp = reinterpret_cast<float*>(g_in2);
    const int t = t0 + 4 * tid;
#pragma unroll
    for (int s = 0; s < SUB; s++) {
        float f0, f1, f2, f3;
        upk2(acc_a[s], f0, f1);
        upk2(acc_b[s], f2, f3);
        size_t base = ((size_t)s * T_DATA + t) * 2 + CIDX;
        if (t + 0 < T_DATA) gp[base + 0] = f0;
        if (t + 1 < T_DATA) gp[base + 2] = f1;
        if (t + 2 < T_DATA) gp[base + 4] = f2;
        if (t + 3 < T_DATA) gp[base + 6] = f3;
    }
}

// ---------------------------------------------------------------------------
// Causal conv, e and i fused through f32x2 lanes:
//   out[t,s] = sum_k ke[s,k]*in_e[t-k,s] + ki[s,k]*in_i[t-k,s]
// Block = (s, 2048-wide time tile); 256 threads x 8 interleaved outputs.
// Data LDS.64 stride-8B/thread => conflict-free; kernel value broadcast.
// ---------------------------------------------------------------------------
#define TT   2048
#define HALO 200

__global__ __launch_bounds__(256) void conv_kernel(float* __restrict__ out) {
    __shared__ unsigned long long sh[TT + HALO];   // 2248 packed (e,i) samples
    __shared__ unsigned long long ksh[TSYN];

    const int s = blockIdx.y;
    const int t0 = blockIdx.x * TT;
    const int tid = threadIdx.x;

    for (int i = tid; i < TT + HALO; i += 256) {
        int t = t0 - HALO + i;
        sh[i] = (t >= 0 && t < T_DATA) ? g_in2[(size_t)s * T_DATA + t] : 0ULL;
    }
    for (int i = tid; i < TSYN; i += 256) ksh[i] = g_kern2[s * TSYN + i];
    __syncthreads();

    unsigned long long acc[8];
#pragma unroll
    for (int j = 0; j < 8; j++) acc[j] = 0ULL;

#pragma unroll 3
    for (int k = 0; k < TSYN; k++) {
        unsigned long long kv = ksh[k];
#pragma unroll
        for (int j = 0; j < 8; j++) {
            unsigned long long dv = sh[tid + 256 * j + HALO - k];
            fma2(acc[j], kv, dv);
        }
    }

#pragma unroll
    for (int j = 0; j < 8; j++) {
        int t = t0 + tid + 256 * j;
        if (t < T_DATA) {
            float lo, hi;
            upk2(acc[j], lo, hi);
            out[(size_t)t * SUB + s] = lo + hi;   // e-lane + i-lane
        }
    }
}

// ---------------------------------------------------------------------------
extern "C" void kernel_launch(void* const* d_in, const int* in_sizes, int n_in,
                              void* d_out, int out_size) {
    const float* S_e     = (const float*)d_in[0];
    const float* S_i     = (const float*)d_in[1];
    const float* C_syn_e = (const float*)d_in[2];
    const float* C_syn_i = (const float*)d_in[3];
    const float* K_syn   = (const float*)d_in[4];
    const float* tau_syn = (const float*)d_in[5];
    const float* delta   = (const float*)d_in[6];
    float* out = (float*)d_out;

    (void)in_sizes; (void)n_in; (void)out_size;

    kern_build<<<(SUB * TSYN * 2 + 255) / 256, 256>>>(K_syn, tau_syn, delta);

    const int gemm_blocks = (T_DATA + 255) / 256;   // 391
    gemm_kernel<N_E, 0><<<gemm_blocks, 64>>>(S_e, C_syn_e);
    gemm_kernel<N_I, 1><<<gemm_blocks, 64>>>(S_i, C_syn_i);

    dim3 cgrid((T_DATA + TT - 1) / TT, SUB);        // 49 x 20
    conv_kernel<<<cgrid, 256>>>(out);
}

// round 6
// speedup vs baseline: 1.2742x; 1.2742x over previous
#include <cuda_runtime.h>

#define T_DATA 100000
#define N_E    500
#define N_I    200
#define SUB    20
#define NB     3
#define TSYN   201

typedef unsigned long long ull;

// ---- GEMM config ----
#define TG    128            // threads per block
#define RG    512            // rows per block (4 per thread)
#define KC    20             // k-chunk (divides 500 and 200)
#define SROW  21             // smem row stride in words (odd -> conflict-free)

// ---- conv config ----
#define TTC   2048           // outputs per block (256 thr x 8 consecutive)
#define KP    208            // taps padded to multiple of 8
#define NWC   282            // residue-layout row width in ull

// Scratch (device globals: allocation-free rule)
__device__ float g_e[(size_t)SUB * T_DATA];
__device__ float g_i[(size_t)SUB * T_DATA];
__device__ ull   g_kern2[SUB * TSYN];          // packed (kern_e, kern_i)

// ---- packed f32x2 helpers ----
__device__ __forceinline__ ull pk2(float lo, float hi) {
    ull r;
    asm("mov.b64 %0, {%1, %2};" : "=l"(r) : "f"(lo), "f"(hi));
    return r;
}
__device__ __forceinline__ void upk2(ull v, float& lo, float& hi) {
    asm("mov.b64 {%0, %1}, %2;" : "=f"(lo), "=f"(hi) : "l"(v));
}
__device__ __forceinline__ void fma2(ull& d, ull a, ull b) {
    asm("fma.rn.f32x2 %0, %1, %2, %0;" : "+l"(d) : "l"(a), "l"(b));
}

// ---------------------------------------------------------------------------
// Kernel bank: kern[s,c,k] = sum_b K_syn[s,b,c] * tt*exp(-tt),
//   tt = max(k - delta[s,c], 0) / exp(tau[b,c]).
// ---------------------------------------------------------------------------
__global__ void kern_build(const float* __restrict__ K_syn,
                           const float* __restrict__ tau_syn,
                           const float* __restrict__ delta_syn) {
    int idx = blockIdx.x * blockDim.x + threadIdx.x;
    if (idx >= SUB * TSYN * 2) return;
    int c = idx & 1;
    int k = (idx >> 1) % TSYN;
    int s = idx / (TSYN * 2);
    float ts = (float)k - delta_syn[s * 2 + c];
    ts = fmaxf(ts, 0.0f);
    float acc = 0.0f;
#pragma unroll
    for (int b = 0; b < NB; b++) {
        float tau = expf(tau_syn[b * 2 + c]);
        float tt = ts / tau;
        acc += K_syn[s * 6 + b * 2 + c] * tt * expf(-tt);
    }
    reinterpret_cast<float*>(g_kern2)[(s * TSYN + k) * 2 + c] = acc;
}

// ---------------------------------------------------------------------------
// Tall-skinny GEMM, e (blockIdx.y=0) and i (=1) fused:
//   in[t,s] = sum_j S[t,j] * C[s,j]
// f32x2 lanes pack SUBUNIT PAIRS (2s2, 2s2+1): the data operand is duplicated
// (smem stays row-major, no transpose); C cached in registers per 2-column
// group and reused across 4 rows/thread. Odd smem stride (21 words) makes the
// lane access conflict-free scalar LDS.
// ---------------------------------------------------------------------------
__global__ __launch_bounds__(TG) void gemm_kernel(const float* __restrict__ Se,
                                                  const float* __restrict__ Si,
                                                  const float* __restrict__ Ce,
                                                  const float* __restrict__ Ci,
                                                  float* __restrict__ oe,
                                                  float* __restrict__ oi) {
    const int which = blockIdx.y;
    const float* __restrict__ Sg = which ? Si : Se;
    const float* __restrict__ Cg = which ? Ci : Ce;
    float* __restrict__ outg = which ? oi : oe;
    const int NIN = which ? N_I : N_E;
    const int nch = NIN / KC;                  // 10 or 25

    __shared__ float S_sh[RG * SROW];          // 512*21*4 = 43008 B
    __shared__ ull   C_sh[SUB / 2][KC];        // 1600 B: (2s2, 2s2+1) pairs

    const int tid = threadIdx.x;
    const int t0 = blockIdx.x * RG;

    ull acc[4][10];
#pragma unroll
    for (int jj = 0; jj < 4; jj++)
#pragma unroll
        for (int s2 = 0; s2 < 10; s2++) acc[jj][s2] = 0ULL;

    for (int ch = 0; ch < nch; ch++) {
        const int kc = ch * KC;
        __syncthreads();
        // stage S tile: 512 rows x 20 cols = 2560 float4, 20 per thread
#pragma unroll
        for (int q = 0; q < 20; q++) {
            int flat = q * TG + tid;
            int row = flat / 5, c4 = flat % 5;
            int t = t0 + row;
            float4 v = make_float4(0.f, 0.f, 0.f, 0.f);
            if (t < T_DATA)
                v = *reinterpret_cast<const float4*>(
                        Sg + (size_t)t * NIN + kc + 4 * c4);
            float* p = &S_sh[row * SROW + 4 * c4];
            p[0] = v.x; p[1] = v.y; p[2] = v.z; p[3] = v.w;
        }
        // stage C chunk as subunit pairs
        for (int i = tid; i < (SUB / 2) * KC; i += TG) {
            int s2 = i / KC, c = i % KC;
            C_sh[s2][c] = pk2(Cg[(2 * s2) * NIN + kc + c],
                              Cg[(2 * s2 + 1) * NIN + kc + c]);
        }
        __syncthreads();

        // compute: c-pairs outer, C in registers, 4 rows x 10 s-pairs inner
#pragma unroll
        for (int c0 = 0; c0 < KC; c0 += 2) {
            ull cc0[10], cc1[10];
#pragma unroll
            for (int s2 = 0; s2 < 10; s2++) {
                cc0[s2] = C_sh[s2][c0];
                cc1[s2] = C_sh[s2][c0 + 1];
            }
#pragma unroll
            for (int jj = 0; jj < 4; jj++) {
                const float* rp = &S_sh[(tid + TG * jj) * SROW];
                float x0 = rp[c0], x1 = rp[c0 + 1];
                ull xa = pk2(x0, x0), xb = pk2(x1, x1);
#pragma unroll
                for (int s2 = 0; s2 < 10; s2++) {
                    fma2(acc[jj][s2], xa, cc0[s2]);
                    fma2(acc[jj][s2], xb, cc1[s2]);
                }
            }
        }
    }

    // epilogue: planar [s][t], coalesced over tid
#pragma unroll
    for (int jj = 0; jj < 4; jj++) {
        int t = t0 + tid + TG * jj;
        if (t < T_DATA) {
#pragma unroll
            for (int s2 = 0; s2 < 10; s2++) {
                float a, b;
                upk2(acc[jj][s2], a, b);
                outg[(size_t)(2 * s2) * T_DATA + t]     = a;
                outg[(size_t)(2 * s2 + 1) * T_DATA + t] = b;
            }
        }
    }
}

// ---------------------------------------------------------------------------
// Causal conv, e/i fused through f32x2 lanes, register sliding window:
//   out[t,s] = sum_k ke[s,k]*in_e[t-k,s] + ki[s,k]*in_i[t-k,s]
// Thread computes 8 CONSECUTIVE outputs t = t0 + 8*tid + j. Per tap: one new
// smem value + broadcast kernel + 8 FFMA2 into a rotating 8-register window
// (value d(m) lives in slot m&7 -> all indices static, no register moves).
// Smem residue-of-8 layout: sample Lp at sh[(Lp&7)*NWC + (Lp>>3)], so the
// stride-8-sample lane pattern becomes lane-consecutive (conflict-free).
// ---------------------------------------------------------------------------
__global__ __launch_bounds__(256) void conv_kernel(float* __restrict__ out) {
    __shared__ ull sh[8 * NWC];     // 2256 packed (e,i) samples, 18048 B
    __shared__ ull ksh[KP];         // taps padded to 208 with zeros

    const int s = blockIdx.y;
    const int t0 = blockIdx.x * TTC;
    const int tid = threadIdx.x;
    const size_t sT = (size_t)s * T_DATA;

    // fill: Lp = local sample index + 8 front-pad; t = t0 - 208 + Lp
    for (int Lp = tid; Lp < 8 * NWC; Lp += 256) {
        int t = t0 - 208 + Lp;
        float e = 0.f, ii = 0.f;
        if (t >= 0 && t < T_DATA) { e = g_e[sT + t]; ii = g_i[sT + t]; }
        sh[(Lp & 7) * NWC + (Lp >> 3)] = pk2(e, ii);
    }
    for (int k = tid; k < KP; k += 256)
        ksh[k] = (k < TSYN) ? g_kern2[s * TSYN + k] : 0ULL;
    __syncthreads();

    // AT(c): sample at global-local offset 8*tid + c (c may be -8..215)
    //   Lp = 8*tid + c + 8  ->  sh[(c&7)*NWC + tid + 1 + (c>>3)]
#define AT(c) sh[(((c) & 7) * NWC) + tid + 1 + ((c) >> 3)]

    ull P[8], acc[8];
#pragma unroll
    for (int j = 0; j < 8; j++) {
        acc[j] = 0ULL;
        P[j] = AT(200 + j);        // window for k=0: d(HALO..HALO+7), slot m&7
    }

#pragma unroll 2
    for (int kb = 0; kb < KP; kb += 8) {
#pragma unroll
        for (int r = 0; r < 8; r++) {
            ull kv = ksh[kb + r];
#pragma unroll
            for (int j = 0; j < 8; j++)
                fma2(acc[j], kv, P[(j - r) & 7]);
            // slide: load d(199 - k) into slot (199-k)&7 = 7-r
            P[(7 - r)] = AT(199 - kb - r);
        }
    }
#undef AT

#pragma unroll
    for (int j = 0; j < 8; j++) {
        int t = t0 + 8 * tid + j;
        if (t < T_DATA) {
            float lo, hi;
            upk2(acc[j], lo, hi);
            out[(size_t)t * SUB + s] = lo + hi;    // e-lane + i-lane
        }
    }
}

// ---------------------------------------------------------------------------
extern "C" void kernel_launch(void* const* d_in, const int* in_sizes, int n_in,
                              void* d_out, int out_size) {
    const float* S_e     = (const float*)d_in[0];
    const float* S_i     = (const float*)d_in[1];
    const float* C_syn_e = (const float*)d_in[2];
    const float* C_syn_i = (const float*)d_in[3];
    const float* K_syn   = (const float*)d_in[4];
    const float* tau_syn = (const float*)d_in[5];
    const float* delta   = (const float*)d_in[6];
    float* out = (float*)d_out;

    (void)in_sizes; (void)n_in; (void)out_size;

    float* ge; cudaGetSymbolAddress((void**)&ge, g_e);
    float* gi; cudaGetSymbolAddress((void**)&gi, g_i);

    kern_build<<<(SUB * TSYN * 2 + 255) / 256, 256>>>(K_syn, tau_syn, delta);

    dim3 ggrid((T_DATA + RG - 1) / RG, 2);          // 196 x 2 (e and i)
    gemm_kernel<<<ggrid, TG>>>(S_e, S_i, C_syn_e, C_syn_i, ge, gi);

    dim3 cgrid((T_DATA + TTC - 1) / TTC, SUB);      // 49 x 20
    conv_kernel<<<cgrid, 256>>>(out);
}

// round 7
// speedup vs baseline: 2.0721x; 1.6262x over previous
#include <cuda_runtime.h>

#define T_DATA 100000
#define N_E    500
#define N_I    200
#define SUB    20
#define NB     3
#define TSYN   201

typedef unsigned long long ull;

// ---- GEMM config ----
#define TG    128            // threads per block
#define RG    256            // rows per block (2 per thread)
#define KC    20             // k-chunk (divides 500 and 200)

// ---- conv config ----
#define TTC   2048           // outputs per block (256 thr x 8 consecutive)
#define KP    208            // taps padded to multiple of 8
#define NWC   282            // residue-layout row width in ull

// Scratch (device globals: allocation-free rule)
__device__ float g_e[(size_t)SUB * T_DATA];
__device__ float g_i[(size_t)SUB * T_DATA];

// ---- packed f32x2 helpers ----
__device__ __forceinline__ ull pk2(float lo, float hi) {
    ull r;
    asm("mov.b64 %0, {%1, %2};" : "=l"(r) : "f"(lo), "f"(hi));
    return r;
}
__device__ __forceinline__ void upk2(ull v, float& lo, float& hi) {
    asm("mov.b64 {%0, %1}, %2;" : "=f"(lo), "=f"(hi) : "l"(v));
}
__device__ __forceinline__ void fma2(ull& d, ull a, ull b) {
    asm("fma.rn.f32x2 %0, %1, %2, %0;" : "+l"(d) : "l"(a), "l"(b));
}

// component extract, c compile-time
#define GETC(v, c) (((c) & 3) == 0 ? (v)[(c) >> 2].x : \
                    ((c) & 3) == 1 ? (v)[(c) >> 2].y : \
                    ((c) & 3) == 2 ? (v)[(c) >> 2].z : (v)[(c) >> 2].w)

// ---------------------------------------------------------------------------
// Tall-skinny GEMM, e (blockIdx.y=0) and i (=1) fused:
//   in[t,s] = sum_j S[t,j] * C[s,j]
// S has no reuse -> loaded straight GMEM->registers, double-buffered one
// chunk ahead (10 LDG.128/thread overlap compute). Only C goes through smem
// (double-buffered, staged one chunk ahead). f32x2 lanes pack SUBUNIT PAIRS;
// the duplicated data operand comes from registers; C values are broadcast
// LDS (conflict-free).
// ---------------------------------------------------------------------------
__global__ __launch_bounds__(TG) void gemm_kernel(const float* __restrict__ Se,
                                                  const float* __restrict__ Si,
                                                  const float* __restrict__ Ce,
                                                  const float* __restrict__ Ci,
                                                  float* __restrict__ oe,
                                                  float* __restrict__ oi) {
    const int which = blockIdx.y;
    const float* __restrict__ Sg = which ? Si : Se;
    const float* __restrict__ Cg = which ? Ci : Ce;
    float* __restrict__ outg = which ? oi : oe;
    const int NIN = which ? N_I : N_E;
    const int nch = NIN / KC;                    // 10 or 25

    __shared__ ull C_sh[2][SUB / 2][KC];         // 3.2 KB double-buffered

    const int tid = threadIdx.x;
    const int t0 = blockIdx.x * RG;
    const int r0 = t0 + tid;
    const int r1 = t0 + tid + TG;
    const bool ok0 = r0 < T_DATA;
    const bool ok1 = r1 < T_DATA;
    const float* __restrict__ p0 = Sg + (size_t)r0 * NIN;
    const float* __restrict__ p1 = Sg + (size_t)r1 * NIN;

    ull acc[2][10];
#pragma unroll
    for (int r = 0; r < 2; r++)
#pragma unroll
        for (int s2 = 0; s2 < 10; s2++) acc[r][s2] = 0ULL;

    float4 vc[2][5], vn[2][5];
    const float4 z4 = make_float4(0.f, 0.f, 0.f, 0.f);

    // prefetch chunk 0: S into registers, C into smem buffer 0
#pragma unroll
    for (int q = 0; q < 5; q++) {
        vn[0][q] = ok0 ? *reinterpret_cast<const float4*>(p0 + 4 * q) : z4;
        vn[1][q] = ok1 ? *reinterpret_cast<const float4*>(p1 + 4 * q) : z4;
    }
    for (int i = tid; i < (SUB / 2) * KC; i += TG) {
        int s2 = i / KC, c = i % KC;
        C_sh[0][s2][c] = pk2(Cg[(2 * s2) * NIN + c],
                             Cg[(2 * s2 + 1) * NIN + c]);
    }

    int buf = 0;
#pragma unroll 1
    for (int ch = 0; ch < nch; ch++) {
        __syncthreads();   // C_sh[buf] staged; prior compute (read buf^1) done

        // shift prefetched S into compute regs
#pragma unroll
        for (int q = 0; q < 5; q++) { vc[0][q] = vn[0][q]; vc[1][q] = vn[1][q]; }

        // prefetch next chunk (overlaps with compute below)
        if (ch + 1 < nch) {
            const int kc = (ch + 1) * KC;
#pragma unroll
            for (int q = 0; q < 5; q++) {
                vn[0][q] = ok0 ? *reinterpret_cast<const float4*>(p0 + kc + 4 * q) : z4;
                vn[1][q] = ok1 ? *reinterpret_cast<const float4*>(p1 + kc + 4 * q) : z4;
            }
            for (int i = tid; i < (SUB / 2) * KC; i += TG) {
                int s2 = i / KC, c = i % KC;
                C_sh[buf ^ 1][s2][c] = pk2(Cg[(2 * s2) * NIN + kc + c],
                                           Cg[(2 * s2 + 1) * NIN + kc + c]);
            }
        }

        // compute: c-pairs outer (data packed once), s-pairs inner (LDS bcast)
#pragma unroll
        for (int c0 = 0; c0 < KC; c0 += 2) {
            float x00 = GETC(vc[0], c0), x01 = GETC(vc[0], c0 + 1);
            float x10 = GETC(vc[1], c0), x11 = GETC(vc[1], c0 + 1);
            ull a00 = pk2(x00, x00), a01 = pk2(x01, x01);
            ull a10 = pk2(x10, x10), a11 = pk2(x11, x11);
#pragma unroll
            for (int s2 = 0; s2 < 10; s2++) {
                ull cc0 = C_sh[buf][s2][c0];
                ull cc1 = C_sh[buf][s2][c0 + 1];
                fma2(acc[0][s2], a00, cc0);
                fma2(acc[0][s2], a01, cc1);
                fma2(acc[1][s2], a10, cc0);
                fma2(acc[1][s2], a11, cc1);
            }
        }
        buf ^= 1;
    }

    // epilogue: planar [s][t], coalesced over tid
#pragma unroll
    for (int r = 0; r < 2; r++) {
        int t = t0 + tid + TG * r;
        if (t < T_DATA) {
#pragma unroll
            for (int s2 = 0; s2 < 10; s2++) {
                float a, b;
                upk2(acc[r][s2], a, b);
                outg[(size_t)(2 * s2) * T_DATA + t]     = a;
                outg[(size_t)(2 * s2 + 1) * T_DATA + t] = b;
            }
        }
    }
}

// ---------------------------------------------------------------------------
// Causal conv, e/i fused through f32x2 lanes, register sliding window.
// Taps computed in-block (alpha-function bank) — no separate kernel.
// Thread computes 8 CONSECUTIVE outputs; per tap: one new smem value +
// broadcast tap + 8 FFMA2 into a rotating 8-register window (static idx).
// Smem residue-of-8 layout keeps the stride-8 lane pattern conflict-free.
// ---------------------------------------------------------------------------
__global__ __launch_bounds__(256) void conv_kernel(float* __restrict__ out,
                                                   const float* __restrict__ K_syn,
                                                   const float* __restrict__ tau_syn,
                                                   const float* __restrict__ delta_syn) {
    __shared__ ull sh[8 * NWC];     // 2256 packed (e,i) samples, 18048 B
    __shared__ ull ksh[KP];         // taps padded to 208 with zeros

    const int s = blockIdx.y;
    const int t0 = blockIdx.x * TTC;
    const int tid = threadIdx.x;
    const size_t sT = (size_t)s * T_DATA;

    // taps: ksh[k] = (kern_e[s,k], kern_i[s,k])
    if (tid < KP) {
        const int k = tid;
        float ae = 0.f, ai = 0.f;
        if (k < TSYN) {
            float tse = fmaxf((float)k - delta_syn[s * 2 + 0], 0.f);
            float tsi = fmaxf((float)k - delta_syn[s * 2 + 1], 0.f);
#pragma unroll
            for (int b = 0; b < NB; b++) {
                float te = tse / expf(tau_syn[b * 2 + 0]);
                float ti = tsi / expf(tau_syn[b * 2 + 1]);
                ae += K_syn[s * 6 + b * 2 + 0] * te * expf(-te);
                ai += K_syn[s * 6 + b * 2 + 1] * ti * expf(-ti);
            }
        }
        ksh[k] = pk2(ae, ai);
    }

    // fill: Lp = local sample index + 8 front-pad; t = t0 - 208 + Lp
    for (int Lp = tid; Lp < 8 * NWC; Lp += 256) {
        int t = t0 - 208 + Lp;
        float e = 0.f, ii = 0.f;
        if (t >= 0 && t < T_DATA) { e = g_e[sT + t]; ii = g_i[sT + t]; }
        sh[(Lp & 7) * NWC + (Lp >> 3)] = pk2(e, ii);
    }
    __syncthreads();

    // AT(c): sample at local offset 8*tid + c (c may be -8..215)
    //   Lp = 8*tid + c + 8  ->  sh[(c&7)*NWC + tid + 1 + (c>>3)]
#define AT(c) sh[(((c) & 7) * NWC) + tid + 1 + ((c) >> 3)]

    ull P[8], acc[8];
#pragma unroll
    for (int j = 0; j < 8; j++) {
        acc[j] = 0ULL;
        P[j] = AT(200 + j);        // window for k=0: slot m&7 holds d(m)
    }

#pragma unroll 2
    for (int kb = 0; kb < KP; kb += 8) {
#pragma unroll
        for (int r = 0; r < 8; r++) {
            ull kv = ksh[kb + r];
#pragma unroll
            for (int j = 0; j < 8; j++)
                fma2(acc[j], kv, P[(j - r) & 7]);
            // slide: load d(199 - k) into slot (199-k)&7 = 7-r
            P[(7 - r)] = AT(199 - kb - r);
        }
    }
#undef AT

#pragma unroll
    for (int j = 0; j < 8; j++) {
        int t = t0 + 8 * tid + j;
        if (t < T_DATA) {
            float lo, hi;
            upk2(acc[j], lo, hi);
            out[(size_t)t * SUB + s] = lo + hi;    // e-lane + i-lane
        }
    }
}

// ---------------------------------------------------------------------------
extern "C" void kernel_launch(void* const* d_in, const int* in_sizes, int n_in,
                              void* d_out, int out_size) {
    const float* S_e     = (const float*)d_in[0];
    const float* S_i     = (const float*)d_in[1];
    const float* C_syn_e = (const float*)d_in[2];
    const float* C_syn_i = (const float*)d_in[3];
    const float* K_syn   = (const float*)d_in[4];
    const float* tau_syn = (const float*)d_in[5];
    const float* delta   = (const float*)d_in[6];
    float* out = (float*)d_out;

    (void)in_sizes; (void)n_in; (void)out_size;

    float* ge; cudaGetSymbolAddress((void**)&ge, g_e);
    float* gi; cudaGetSymbolAddress((void**)&gi, g_i);

    dim3 ggrid((T_DATA + RG - 1) / RG, 2);          // 391 x 2 (e and i)
    gemm_kernel<<<ggrid, TG>>>(S_e, S_i, C_syn_e, C_syn_i, ge, gi);

    dim3 cgrid((T_DATA + TTC - 1) / TTC, SUB);      // 49 x 20
    conv_kernel<<<cgrid, 256>>>(out, K_syn, tau_syn, delta);
}